// round 14
// baseline (speedup 1.0000x reference)
#include <cuda_runtime.h>
#include <cstdint>

// DynamicRouting (R12): R11 + (1) routing de-duplicated to one warp via SMEM
// Gram staging, (2) software-pipelined k-loop (ping-pong A/B fragments),
// (3) f32x2 + LDS.64 final pass over px-pairs.

namespace {
constexpr int Gn   = 8;
constexpr int FIn  = 64;
constexpr int FOn  = 64;
constexpr int HWn  = 4096;
constexpr int Bn   = 16;
constexpr int PXT  = 32;
constexpr int THREADS = 256;

// word offsets
constexpr int CONo = 0;                        // 512 rows x 32 = 16384 words
constexpr int Xo   = 16384;                    // 2 halves x 64x32 = 4096 words
constexpr int Wo   = Xo + 2 * FIn * PXT;       // 20480: 2 halves x 64x64 = 8192
constexpr int GRo  = Xo;                       // Gram staging: 32*37 = 1184 w
constexpr int ALo  = Xo + 1184;                // alphas: 8*32 = 256 w
constexpr int SMEM_WORDS = Wo + 2 * FOn * FIn; // 28672
constexpr int SMEM_BYTES = SMEM_WORDS * 4;     // 114688 B -> 2 CTAs/SM
}

// pre-converted tf32 weights (raw bits)
__device__ uint32_t g_wtf[Gn * FOn * FIn];

__device__ __forceinline__ uint32_t cvt_tf32(float f) {
    uint32_t r;
    asm("cvt.rna.tf32.f32 %0, %1;" : "=r"(r) : "f"(f));
    return r;
}

__device__ __forceinline__ uint32_t smem_u32(const void* p) {
    uint32_t a;
    asm("{ .reg .u64 t; cvta.to.shared.u64 t, %1; cvt.u32.u64 %0, t; }"
        : "=r"(a) : "l"(p));
    return a;
}

__device__ __forceinline__ void cp16(uint32_t dst, const void* src) {
    asm volatile("cp.async.cg.shared.global [%0], [%1], 16;"
                 :: "r"(dst), "l"(src) : "memory");
}

__device__ __forceinline__ void ldmatrix_x4(uint32_t& r0, uint32_t& r1,
                                            uint32_t& r2, uint32_t& r3,
                                            uint32_t addr) {
    asm volatile("ldmatrix.sync.aligned.m8n8.x4.shared.b16 {%0,%1,%2,%3}, [%4];"
                 : "=r"(r0), "=r"(r1), "=r"(r2), "=r"(r3) : "r"(addr));
}

__device__ __forceinline__ void mma_tf32(float c[4],
                                         uint32_t a0, uint32_t a1,
                                         uint32_t a2, uint32_t a3,
                                         uint32_t b0, uint32_t b1) {
    asm volatile(
        "mma.sync.aligned.m16n8k8.row.col.f32.tf32.tf32.f32 "
        "{%0,%1,%2,%3}, {%4,%5,%6,%7}, {%8,%9}, {%0,%1,%2,%3};"
        : "+f"(c[0]), "+f"(c[1]), "+f"(c[2]), "+f"(c[3])
        : "r"(a0), "r"(a1), "r"(a2), "r"(a3), "r"(b0), "r"(b1));
}

__device__ __forceinline__ uint64_t f2_fma(uint64_t a, uint64_t b, uint64_t c) {
    uint64_t d;
    asm("fma.rn.f32x2 %0, %1, %2, %3;" : "=l"(d) : "l"(a), "l"(b), "l"(c));
    return d;
}

__device__ __forceinline__ float sigmoidf_(float v) {
    return 1.f / (1.f + __expf(-v));
}

__device__ __forceinline__ int pidx(int a, int b) {
    int lo = a < b ? a : b, hi = a < b ? b : a;
    return lo * 8 - lo * (lo - 1) / 2 + (hi - lo);
}

__device__ __forceinline__ int con_addr(int row, int px) {
    return CONo + row * 32 + (px ^ (4 * (row & 7)));
}

// ---------------- pre-kernel: W -> tf32 scratch ------------------------------
__global__ void wconv_kernel(const float* __restrict__ w) {
    int i = blockIdx.x * blockDim.x + threadIdx.x;
    g_wtf[i] = cvt_tf32(w[i]);
}

// ---------------- main kernel ------------------------------------------------
__global__ void __launch_bounds__(THREADS, 2)
dynrout_mma_kernel(const float* __restrict__ x,
                   const float* __restrict__ bias,
                   float* __restrict__ out)
{
    extern __shared__ uint32_t smu[];
    float* smf = reinterpret_cast<float*>(smu);
    const uint32_t sbase = smem_u32(smu);

    const int t    = threadIdx.x;
    const int wid  = t >> 5;
    const int lane = t & 31;
    const int gid  = lane >> 2;
    const int tid4 = lane & 3;

    const int cta = blockIdx.x;
    const int bi  = cta >> 7;
    const int p0  = (cta & 127) * PXT;

    const int half = wid >> 2;
    const int w2   = wid & 3;
    const int pxb  = (w2 & 1) * 16;
    const int fob  = (w2 >> 1) * 32;

    const int oct = lane >> 3;
    const int oo  = oct & 1;
    const int nt  = oct >> 1;
    const int r8  = lane & 7;

    // ---------------- cp.async tile loads (both halves, swizzled) ------------
    auto issue_iter = [&](int it) {
        #pragma unroll
        for (int h = 0; h < 2; h++) {
            const int g = 2 * it + h;
            const float* xg = x + ((size_t)(bi * Gn + g) * FIn) * HWn + p0;
            const uint32_t* wg = g_wtf + g * (FOn * FIn);
            const uint32_t xo = sbase + (Xo + h * (FIn * PXT)) * 4;
            const uint32_t wo = sbase + (Wo + h * (FOn * FIn)) * 4;
            #pragma unroll
            for (int k = 0; k < 2; k++) {
                int q  = t + k * THREADS;
                int fi = q >> 3;
                int c4 = (q & 7) * 4;
                cp16(xo + (fi * 32 + (c4 ^ (8 * (fi & 3)))) * 4,
                     xg + (size_t)fi * HWn + c4);
            }
            #pragma unroll
            for (int k = 0; k < 4; k++) {
                int q  = t + k * THREADS;
                int fo = q >> 4;
                int c4 = (q & 15) * 4;
                cp16(wo + (fo * 64 + (c4 ^ (4 * (fo & 7)))) * 4,
                     wg + fo * FIn + c4);
            }
        }
        asm volatile("cp.async.commit_group;" ::: "memory");
    };

    // ---------------- GEMM: 4 iterations, software-pipelined k-loop ----------
    issue_iter(0);

    for (int it = 0; it < 4; it++) {
        asm volatile("cp.async.wait_group 0;" ::: "memory");
        __syncthreads();

        const int g  = 2 * it + half;
        const int xo = Xo + half * (FIn * PXT);
        const int wo = Wo + half * (FOn * FIn);

        const uint32_t bw0 = sbase + (uint32_t)(wo + (fob +      nt * 8 + r8) * 64) * 4;
        const uint32_t bw1 = sbase + (uint32_t)(wo + (fob + 16 + nt * 8 + r8) * 64) * 4;
        const int sxa = 8 * tid4;
        const int pA  = (pxb + gid) ^ sxa;
        const int pB  = (pxb + gid + 8) ^ sxa;

        float acc[4][4];
        #pragma unroll
        for (int n = 0; n < 4; n++)
            #pragma unroll
            for (int j = 0; j < 4; j++) acc[n][j] = 0.f;

        uint32_t arw[2][4];
        uint32_t bfr[2][8];

        auto loadA = [&](int s, uint32_t* d) {
            const int fi0 = s * 8;
            d[0] = smu[xo + (fi0 + tid4)     * 32 + pA];
            d[1] = smu[xo + (fi0 + tid4)     * 32 + pB];
            d[2] = smu[xo + (fi0 + 4 + tid4) * 32 + pA];
            d[3] = smu[xo + (fi0 + 4 + tid4) * 32 + pB];
        };
        auto loadB = [&](int s, uint32_t* d) {
            const uint32_t coff = 16u * (uint32_t)((2 * s + oo) ^ r8);
            ldmatrix_x4(d[0], d[1], d[2], d[3], bw0 + coff);
            ldmatrix_x4(d[4], d[5], d[6], d[7], bw1 + coff);
        };

        loadA(0, arw[0]);
        loadB(0, bfr[0]);

        #pragma unroll
        for (int s = 0; s < 8; s++) {
            const int cur = s & 1;
            const int nxt = cur ^ 1;
            if (s < 7) { loadA(s + 1, arw[nxt]); loadB(s + 1, bfr[nxt]); }

            uint32_t a0 = cvt_tf32(__uint_as_float(arw[cur][0]));
            uint32_t a1 = cvt_tf32(__uint_as_float(arw[cur][1]));
            uint32_t a2 = cvt_tf32(__uint_as_float(arw[cur][2]));
            uint32_t a3 = cvt_tf32(__uint_as_float(arw[cur][3]));

            mma_tf32(acc[0], a0, a1, a2, a3, bfr[cur][0], bfr[cur][1]);
            mma_tf32(acc[1], a0, a1, a2, a3, bfr[cur][2], bfr[cur][3]);
            mma_tf32(acc[2], a0, a1, a2, a3, bfr[cur][4], bfr[cur][5]);
            mma_tf32(acc[3], a0, a1, a2, a3, bfr[cur][6], bfr[cur][7]);
        }

        // store con (swizzled, conflict-free)
        #pragma unroll
        for (int n = 0; n < 4; n++) {
            const int fo   = fob + n * 8 + 2 * tid4;
            const int row0 = g * FOn + fo;
            const int row1 = row0 + 1;
            smf[con_addr(row0, pxb + gid)]     = acc[n][0];
            smf[con_addr(row1, pxb + gid)]     = acc[n][1];
            smf[con_addr(row0, pxb + gid + 8)] = acc[n][2];
            smf[con_addr(row1, pxb + gid + 8)] = acc[n][3];
        }

        __syncthreads();
        if (it < 3) issue_iter(it + 1);
    }

    // ---------------- Gram pass (8 threads per px) -> SMEM staging -----------
    {
        const int px  = t >> 3;             // 0..31
        const int foc = t & 7;              // 8-fo chunk
        float acc[36];
        #pragma unroll
        for (int p = 0; p < 36; p++) acc[p] = 0.f;

        #pragma unroll
        for (int i = 0; i < 8; i++) {
            const int fo = foc * 8 + ((i + foc) & 7);
            float cg[Gn];
            #pragma unroll
            for (int g = 0; g < Gn; g++)
                cg[g] = smf[con_addr(g * FOn + fo, px)];
            int p = 0;
            #pragma unroll
            for (int a = 0; a < Gn; a++)
                #pragma unroll
                for (int b = a; b < Gn; b++)
                    acc[p++] += cg[a] * cg[b];
        }
        #pragma unroll
        for (int p = 0; p < 36; p++) {
            acc[p] += __shfl_xor_sync(0xFFFFFFFFu, acc[p], 1);
            acc[p] += __shfl_xor_sync(0xFFFFFFFFu, acc[p], 2);
            acc[p] += __shfl_xor_sync(0xFFFFFFFFu, acc[p], 4);
        }

        // stage Gram to SMEM (pad 37 -> conflict-free), split across octet
        if (foc < 4) {
            #pragma unroll
            for (int m = 0; m < 5; m++) {
                int k = foc * 5 + m;
                smf[GRo + px * 37 + k] = acc[k];
            }
        } else {
            #pragma unroll
            for (int m = 0; m < 4; m++) {
                int k = 20 + (foc - 4) * 4 + m;
                smf[GRo + px * 37 + k] = acc[k];
            }
        }
    }
    __syncthreads();

    // ---------------- routing: ONE warp, one thread per pixel ----------------
    if (t < PXT) {
        const int px = t;
        float G[36];
        #pragma unroll
        for (int p = 0; p < 36; p++) G[p] = smf[GRo + px * 37 + p];

        float beta[Gn], alpha[Gn];
        #pragma unroll
        for (int g = 0; g < Gn; g++) {
            float s = 0.f;
            #pragma unroll
            for (int g2 = 0; g2 < Gn; g2++) s += G[pidx(g2, g)];
            beta[g] = 0.5f * s;
        }
        #pragma unroll
        for (int g = 0; g < Gn; g++) alpha[g] = sigmoidf_(beta[g]);
        #pragma unroll
        for (int g = 0; g < Gn; g++) {
            float s = 0.f;
            #pragma unroll
            for (int g2 = 0; g2 < Gn; g2++) s += alpha[g2] * G[pidx(g2, g)];
            beta[g] += s;
        }
        #pragma unroll
        for (int g = 0; g < Gn; g++)
            smf[ALo + g * PXT + px] = sigmoidf_(beta[g]);
    }
    __syncthreads();

    // ---------------- final pass: f32x2 over px-pairs -------------------------
    {
        const int pp = t & 15;              // px-pair: px = 2pp, 2pp+1
        const int fq = t >> 4;              // fo quad: fo = fq*4 + i

        uint64_t al2[Gn];
        #pragma unroll
        for (int g = 0; g < Gn; g++)
            al2[g] = *reinterpret_cast<const uint64_t*>(
                &smf[ALo + g * PXT + 2 * pp]);

        float* ob = out + (size_t)bi * FOn * HWn + p0 + 2 * pp;
        #pragma unroll
        for (int i = 0; i < 4; i++) {
            const int fo = fq * 4 + i;
            uint64_t s2 = 0ull;
            #pragma unroll
            for (int g = 0; g < Gn; g++) {
                const int row = g * FOn + fo;
                const uint64_t c2 = *reinterpret_cast<const uint64_t*>(
                    &smf[CONo + row * 32 + ((2 * pp) ^ (4 * (row & 7)))]);
                s2 = f2_fma(al2[g], c2, s2);
            }
            float slo, shi;
            asm("mov.b64 {%0, %1}, %2;" : "=f"(slo), "=f"(shi) : "l"(s2));
            const float bv = __ldg(&bias[fo]);
            *reinterpret_cast<float2*>(ob + (size_t)fo * HWn) =
                make_float2(slo + bv, shi + bv);
        }
    }
}

extern "C" void kernel_launch(void* const* d_in, const int* in_sizes, int n_in,
                              void* d_out, int out_size)
{
    const float* x = nullptr;
    const float* w = nullptr;
    const float* b = nullptr;
    for (int i = 0; i < n_in; i++) {
        if (in_sizes[i] == Bn * Gn * FIn * HWn)      x = (const float*)d_in[i];
        else if (in_sizes[i] == Gn * FOn * FIn)      w = (const float*)d_in[i];
        else if (in_sizes[i] == FOn)                 b = (const float*)d_in[i];
    }
    float* out = (float*)d_out;

    static bool attr_set = false;
    if (!attr_set) {
        cudaFuncSetAttribute(dynrout_mma_kernel,
                             cudaFuncAttributeMaxDynamicSharedMemorySize, SMEM_BYTES);
        attr_set = true;
    }

    wconv_kernel<<<(Gn * FOn * FIn) / 256, 256>>>(w);

    const int n_ctas = (Bn * HWn) / PXT;   // 2048
    dynrout_mma_kernel<<<n_ctas, THREADS, SMEM_BYTES>>>(x, b, out);
}

// round 15
// speedup vs baseline: 1.2203x; 1.2203x over previous
#include <cuda_runtime.h>
#include <cstdint>

// DynamicRouting (R14): R11 base (82.7us) + (1) per-half cp.async loading with
// named barriers (halves decoupled; block sync only before epilogue),
// (2) f32x2 + LDS.64 final pass. GEMM k-loop / Gram / routing identical to R11.

namespace {
constexpr int Gn   = 8;
constexpr int FIn  = 64;
constexpr int FOn  = 64;
constexpr int HWn  = 4096;
constexpr int Bn   = 16;
constexpr int PXT  = 32;
constexpr int THREADS = 256;

// word offsets
constexpr int CONo = 0;                        // 512 rows x 32 = 16384 words
constexpr int Xo   = 16384;                    // 2 halves x 64x32 = 4096 words
constexpr int Wo   = Xo + 2 * FIn * PXT;       // 20480: 2 halves x 64x64 = 8192
constexpr int ALo  = Xo;                       // alpha reuses X region (256 w)
constexpr int SMEM_WORDS = Wo + 2 * FOn * FIn; // 28672
constexpr int SMEM_BYTES = SMEM_WORDS * 4;     // 114688 B -> 2 CTAs/SM
}

// pre-converted tf32 weights (raw bits)
__device__ uint32_t g_wtf[Gn * FOn * FIn];

__device__ __forceinline__ uint32_t cvt_tf32(float f) {
    uint32_t r;
    asm("cvt.rna.tf32.f32 %0, %1;" : "=r"(r) : "f"(f));
    return r;
}

__device__ __forceinline__ uint32_t smem_u32(const void* p) {
    uint32_t a;
    asm("{ .reg .u64 t; cvta.to.shared.u64 t, %1; cvt.u32.u64 %0, t; }"
        : "=r"(a) : "l"(p));
    return a;
}

__device__ __forceinline__ void cp16(uint32_t dst, const void* src) {
    asm volatile("cp.async.cg.shared.global [%0], [%1], 16;"
                 :: "r"(dst), "l"(src) : "memory");
}

__device__ __forceinline__ void ldmatrix_x4(uint32_t& r0, uint32_t& r1,
                                            uint32_t& r2, uint32_t& r3,
                                            uint32_t addr) {
    asm volatile("ldmatrix.sync.aligned.m8n8.x4.shared.b16 {%0,%1,%2,%3}, [%4];"
                 : "=r"(r0), "=r"(r1), "=r"(r2), "=r"(r3) : "r"(addr));
}

__device__ __forceinline__ void mma_tf32(float c[4],
                                         uint32_t a0, uint32_t a1,
                                         uint32_t a2, uint32_t a3,
                                         uint32_t b0, uint32_t b1) {
    asm volatile(
        "mma.sync.aligned.m16n8k8.row.col.f32.tf32.tf32.f32 "
        "{%0,%1,%2,%3}, {%4,%5,%6,%7}, {%8,%9}, {%0,%1,%2,%3};"
        : "+f"(c[0]), "+f"(c[1]), "+f"(c[2]), "+f"(c[3])
        : "r"(a0), "r"(a1), "r"(a2), "r"(a3), "r"(b0), "r"(b1));
}

__device__ __forceinline__ uint64_t f2_fma(uint64_t a, uint64_t b, uint64_t c) {
    uint64_t d;
    asm("fma.rn.f32x2 %0, %1, %2, %3;" : "=l"(d) : "l"(a), "l"(b), "l"(c));
    return d;
}

__device__ __forceinline__ float sigmoidf_(float v) {
    return 1.f / (1.f + __expf(-v));
}

__device__ __forceinline__ int pidx(int a, int b) {
    int lo = a < b ? a : b, hi = a < b ? b : a;
    return lo * 8 - lo * (lo - 1) / 2 + (hi - lo);
}

__device__ __forceinline__ int con_addr(int row, int px) {
    return CONo + row * 32 + (px ^ (4 * (row & 7)));
}

// ---------------- pre-kernel: W -> tf32 scratch ------------------------------
__global__ void wconv_kernel(const float* __restrict__ w) {
    int i = blockIdx.x * blockDim.x + threadIdx.x;
    g_wtf[i] = cvt_tf32(w[i]);
}

// ---------------- main kernel ------------------------------------------------
__global__ void __launch_bounds__(THREADS, 2)
dynrout_mma_kernel(const float* __restrict__ x,
                   const float* __restrict__ bias,
                   float* __restrict__ out)
{
    extern __shared__ uint32_t smu[];
    float* smf = reinterpret_cast<float*>(smu);
    const uint32_t sbase = smem_u32(smu);

    const int t    = threadIdx.x;
    const int wid  = t >> 5;
    const int lane = t & 31;
    const int gid  = lane >> 2;
    const int tid4 = lane & 3;

    const int cta = blockIdx.x;
    const int bi  = cta >> 7;
    const int p0  = (cta & 127) * PXT;

    const int half = wid >> 2;          // 0: even groups, 1: odd groups
    const int lt   = t & 127;           // thread id within half
    const int w2   = wid & 3;
    const int pxb  = (w2 & 1) * 16;
    const int fob  = (w2 >> 1) * 32;

    const int oct = lane >> 3;
    const int oo  = oct & 1;
    const int nt  = oct >> 1;
    const int r8  = lane & 7;

    const int xo = Xo + half * (FIn * PXT);
    const int wo = Wo + half * (FOn * FIn);
    const uint32_t xob = sbase + (uint32_t)xo * 4;
    const uint32_t wob = sbase + (uint32_t)wo * 4;

    // named barrier for this half (128 threads)
    auto barx = [&]() {
        asm volatile("bar.sync %0, 128;" :: "r"(half + 1) : "memory");
    };

    // ---------------- per-half cp.async loads (own buffers only) -------------
    auto issue_half = [&](int g) {
        const float* xg = x + ((size_t)(bi * Gn + g) * FIn) * HWn + p0;
        const uint32_t* wg = g_wtf + g * (FOn * FIn);
        #pragma unroll
        for (int k = 0; k < 4; k++) {           // X: 512 chunks / 128 thr
            int q  = lt + k * 128;
            int fi = q >> 3;
            int c4 = (q & 7) * 4;
            cp16(xob + (fi * 32 + (c4 ^ (8 * (fi & 3)))) * 4,
                 xg + (size_t)fi * HWn + c4);
        }
        #pragma unroll
        for (int k = 0; k < 8; k++) {           // W: 1024 chunks / 128 thr
            int q  = lt + k * 128;
            int fo = q >> 4;
            int c4 = (q & 15) * 4;
            cp16(wob + (fo * 64 + (c4 ^ (4 * (fo & 7)))) * 4,
                 wg + fo * FIn + c4);
        }
        asm volatile("cp.async.commit_group;" ::: "memory");
    };

    // ---------------- GEMM: 4 iterations, group = 2*it + half ----------------
    issue_half(half);

    const uint32_t bw0 = sbase + (uint32_t)(wo + (fob +      nt * 8 + r8) * 64) * 4;
    const uint32_t bw1 = sbase + (uint32_t)(wo + (fob + 16 + nt * 8 + r8) * 64) * 4;
    const int sxa = 8 * tid4;
    const int pA  = (pxb + gid) ^ sxa;
    const int pB  = (pxb + gid + 8) ^ sxa;

    for (int it = 0; it < 4; it++) {
        const int g = 2 * it + half;

        asm volatile("cp.async.wait_group 0;" ::: "memory");
        barx();                             // all 4 warps of half have data

        float acc[4][4];
        #pragma unroll
        for (int n = 0; n < 4; n++)
            #pragma unroll
            for (int j = 0; j < 4; j++) acc[n][j] = 0.f;

        #pragma unroll
        for (int s = 0; s < 8; s++) {
            const int fi0 = s * 8;
            uint32_t a0 = cvt_tf32(smf[xo + (fi0 + tid4)     * 32 + pA]);
            uint32_t a1 = cvt_tf32(smf[xo + (fi0 + tid4)     * 32 + pB]);
            uint32_t a2 = cvt_tf32(smf[xo + (fi0 + 4 + tid4) * 32 + pA]);
            uint32_t a3 = cvt_tf32(smf[xo + (fi0 + 4 + tid4) * 32 + pB]);

            const uint32_t coff = 16u * (uint32_t)((2 * s + oo) ^ r8);
            uint32_t b0, b1, b2, b3, b4, b5, b6, b7;
            ldmatrix_x4(b0, b1, b2, b3, bw0 + coff);
            ldmatrix_x4(b4, b5, b6, b7, bw1 + coff);

            mma_tf32(acc[0], a0, a1, a2, a3, b0, b1);
            mma_tf32(acc[1], a0, a1, a2, a3, b2, b3);
            mma_tf32(acc[2], a0, a1, a2, a3, b4, b5);
            mma_tf32(acc[3], a0, a1, a2, a3, b6, b7);
        }

        barx();                             // all 4 warps done reading buffers
        if (it < 3) issue_half(2 * (it + 1) + half);   // overlaps con store

        // store con (swizzled, conflict-free)
        #pragma unroll
        for (int n = 0; n < 4; n++) {
            const int fo   = fob + n * 8 + 2 * tid4;
            const int row0 = g * FOn + fo;
            const int row1 = row0 + 1;
            smf[con_addr(row0, pxb + gid)]     = acc[n][0];
            smf[con_addr(row1, pxb + gid)]     = acc[n][1];
            smf[con_addr(row0, pxb + gid + 8)] = acc[n][2];
            smf[con_addr(row1, pxb + gid + 8)] = acc[n][3];
        }
    }

    __syncthreads();    // con complete, both halves

    // ---------------- Gram pass (8 threads per px) ---------------------------
    {
        const int px  = t >> 3;             // 0..31
        const int foc = t & 7;              // 8-fo chunk
        float acc[36];
        #pragma unroll
        for (int p = 0; p < 36; p++) acc[p] = 0.f;

        #pragma unroll
        for (int i = 0; i < 8; i++) {
            const int fo = foc * 8 + ((i + foc) & 7);   // stagger: conflict-free
            float cg[Gn];
            #pragma unroll
            for (int g = 0; g < Gn; g++)
                cg[g] = smf[con_addr(g * FOn + fo, px)];
            int p = 0;
            #pragma unroll
            for (int a = 0; a < Gn; a++)
                #pragma unroll
                for (int b = a; b < Gn; b++)
                    acc[p++] += cg[a] * cg[b];
        }
        #pragma unroll
        for (int p = 0; p < 36; p++) {
            acc[p] += __shfl_xor_sync(0xFFFFFFFFu, acc[p], 1);
            acc[p] += __shfl_xor_sync(0xFFFFFFFFu, acc[p], 2);
            acc[p] += __shfl_xor_sync(0xFFFFFFFFu, acc[p], 4);
        }

        // routing on 8x8 Gram (redundant across octet; foc==0 stores alpha)
        float beta[Gn], alpha[Gn];
        #pragma unroll
        for (int g = 0; g < Gn; g++) {
            float s = 0.f;
            #pragma unroll
            for (int g2 = 0; g2 < Gn; g2++) s += acc[pidx(g2, g)];
            beta[g] = 0.5f * s;
        }
        #pragma unroll
        for (int g = 0; g < Gn; g++) alpha[g] = sigmoidf_(beta[g]);
        #pragma unroll
        for (int g = 0; g < Gn; g++) {
            float s = 0.f;
            #pragma unroll
            for (int g2 = 0; g2 < Gn; g2++) s += alpha[g2] * acc[pidx(g2, g)];
            beta[g] += s;
        }
        if (foc == 0) {
            #pragma unroll
            for (int g = 0; g < Gn; g++)
                smf[ALo + g * PXT + px] = sigmoidf_(beta[g]);
        }
    }
    __syncthreads();

    // ---------------- final pass: f32x2 over px-pairs -------------------------
    {
        const int pp = t & 15;              // px-pair: px = 2pp, 2pp+1
        const int fq = t >> 4;              // fo quad: fo = fq*4 + i

        uint64_t al2[Gn];
        #pragma unroll
        for (int g = 0; g < Gn; g++)
            al2[g] = *reinterpret_cast<const uint64_t*>(
                &smf[ALo + g * PXT + 2 * pp]);

        float* ob = out + (size_t)bi * FOn * HWn + p0 + 2 * pp;
        #pragma unroll
        for (int i = 0; i < 4; i++) {
            const int fo = fq * 4 + i;
            uint64_t s2 = 0ull;
            #pragma unroll
            for (int g = 0; g < Gn; g++) {
                const int row = g * FOn + fo;
                const uint64_t c2 = *reinterpret_cast<const uint64_t*>(
                    &smf[CONo + row * 32 + ((2 * pp) ^ (4 * (row & 7)))]);
                s2 = f2_fma(al2[g], c2, s2);
            }
            float slo, shi;
            asm("mov.b64 {%0, %1}, %2;" : "=f"(slo), "=f"(shi) : "l"(s2));
            const float bv = __ldg(&bias[fo]);
            *reinterpret_cast<float2*>(ob + (size_t)fo * HWn) =
                make_float2(slo + bv, shi + bv);
        }
    }
}

extern "C" void kernel_launch(void* const* d_in, const int* in_sizes, int n_in,
                              void* d_out, int out_size)
{
    const float* x = nullptr;
    const float* w = nullptr;
    const float* b = nullptr;
    for (int i = 0; i < n_in; i++) {
        if (in_sizes[i] == Bn * Gn * FIn * HWn)      x = (const float*)d_in[i];
        else if (in_sizes[i] == Gn * FOn * FIn)      w = (const float*)d_in[i];
        else if (in_sizes[i] == FOn)                 b = (const float*)d_in[i];
    }
    float* out = (float*)d_out;

    static bool attr_set = false;
    if (!attr_set) {
        cudaFuncSetAttribute(dynrout_mma_kernel,
                             cudaFuncAttributeMaxDynamicSharedMemorySize, SMEM_BYTES);
        attr_set = true;
    }

    wconv_kernel<<<(Gn * FOn * FIn) / 256, 256>>>(w);

    const int n_ctas = (Bn * HWn) / PXT;   // 2048
    dynrout_mma_kernel<<<n_ctas, THREADS, SMEM_BYTES>>>(x, b, out);
}

// round 16
// speedup vs baseline: 1.2990x; 1.0644x over previous
#include <cuda_runtime.h>
#include <cstdint>

// DynamicRouting (R15): R14 base + epilogue restructure: Gram matrix replaced
// by direct fused v-formulation (two con sweeps, each fusing the v-matvec and
// the beta-dot). ~110 fewer inst/thread, half the shuffle chains.

namespace {
constexpr int Gn   = 8;
constexpr int FIn  = 64;
constexpr int FOn  = 64;
constexpr int HWn  = 4096;
constexpr int Bn   = 16;
constexpr int PXT  = 32;
constexpr int THREADS = 256;

// word offsets
constexpr int CONo = 0;                        // 512 rows x 32 = 16384 words
constexpr int Xo   = 16384;                    // 2 halves x 64x32 = 4096 words
constexpr int Wo   = Xo + 2 * FIn * PXT;       // 20480: 2 halves x 64x64 = 8192
constexpr int ALo  = Xo;                       // alpha reuses X region (256 w)
constexpr int SMEM_WORDS = Wo + 2 * FOn * FIn; // 28672
constexpr int SMEM_BYTES = SMEM_WORDS * 4;     // 114688 B -> 2 CTAs/SM
}

// pre-converted tf32 weights (raw bits)
__device__ uint32_t g_wtf[Gn * FOn * FIn];

__device__ __forceinline__ uint32_t cvt_tf32(float f) {
    uint32_t r;
    asm("cvt.rna.tf32.f32 %0, %1;" : "=r"(r) : "f"(f));
    return r;
}

__device__ __forceinline__ uint32_t smem_u32(const void* p) {
    uint32_t a;
    asm("{ .reg .u64 t; cvta.to.shared.u64 t, %1; cvt.u32.u64 %0, t; }"
        : "=r"(a) : "l"(p));
    return a;
}

__device__ __forceinline__ void cp16(uint32_t dst, const void* src) {
    asm volatile("cp.async.cg.shared.global [%0], [%1], 16;"
                 :: "r"(dst), "l"(src) : "memory");
}

__device__ __forceinline__ void ldmatrix_x4(uint32_t& r0, uint32_t& r1,
                                            uint32_t& r2, uint32_t& r3,
                                            uint32_t addr) {
    asm volatile("ldmatrix.sync.aligned.m8n8.x4.shared.b16 {%0,%1,%2,%3}, [%4];"
                 : "=r"(r0), "=r"(r1), "=r"(r2), "=r"(r3) : "r"(addr));
}

__device__ __forceinline__ void mma_tf32(float c[4],
                                         uint32_t a0, uint32_t a1,
                                         uint32_t a2, uint32_t a3,
                                         uint32_t b0, uint32_t b1) {
    asm volatile(
        "mma.sync.aligned.m16n8k8.row.col.f32.tf32.tf32.f32 "
        "{%0,%1,%2,%3}, {%4,%5,%6,%7}, {%8,%9}, {%0,%1,%2,%3};"
        : "+f"(c[0]), "+f"(c[1]), "+f"(c[2]), "+f"(c[3])
        : "r"(a0), "r"(a1), "r"(a2), "r"(a3), "r"(b0), "r"(b1));
}

__device__ __forceinline__ uint64_t f2_fma(uint64_t a, uint64_t b, uint64_t c) {
    uint64_t d;
    asm("fma.rn.f32x2 %0, %1, %2, %3;" : "=l"(d) : "l"(a), "l"(b), "l"(c));
    return d;
}

__device__ __forceinline__ float sigmoidf_(float v) {
    return 1.f / (1.f + __expf(-v));
}

__device__ __forceinline__ int con_addr(int row, int px) {
    return CONo + row * 32 + (px ^ (4 * (row & 7)));
}

// ---------------- pre-kernel: W -> tf32 scratch ------------------------------
__global__ void wconv_kernel(const float* __restrict__ w) {
    int i = blockIdx.x * blockDim.x + threadIdx.x;
    g_wtf[i] = cvt_tf32(w[i]);
}

// ---------------- main kernel ------------------------------------------------
__global__ void __launch_bounds__(THREADS, 2)
dynrout_mma_kernel(const float* __restrict__ x,
                   const float* __restrict__ bias,
                   float* __restrict__ out)
{
    extern __shared__ uint32_t smu[];
    float* smf = reinterpret_cast<float*>(smu);
    const uint32_t sbase = smem_u32(smu);

    const int t    = threadIdx.x;
    const int wid  = t >> 5;
    const int lane = t & 31;
    const int gid  = lane >> 2;
    const int tid4 = lane & 3;

    const int cta = blockIdx.x;
    const int bi  = cta >> 7;
    const int p0  = (cta & 127) * PXT;

    const int half = wid >> 2;          // 0: even groups, 1: odd groups
    const int lt   = t & 127;
    const int w2   = wid & 3;
    const int pxb  = (w2 & 1) * 16;
    const int fob  = (w2 >> 1) * 32;

    const int oct = lane >> 3;
    const int oo  = oct & 1;
    const int nt  = oct >> 1;
    const int r8  = lane & 7;

    const int xo = Xo + half * (FIn * PXT);
    const int wo = Wo + half * (FOn * FIn);
    const uint32_t xob = sbase + (uint32_t)xo * 4;
    const uint32_t wob = sbase + (uint32_t)wo * 4;

    auto barx = [&]() {
        asm volatile("bar.sync %0, 128;" :: "r"(half + 1) : "memory");
    };

    // ---------------- per-half cp.async loads --------------------------------
    auto issue_half = [&](int g) {
        const float* xg = x + ((size_t)(bi * Gn + g) * FIn) * HWn + p0;
        const uint32_t* wg = g_wtf + g * (FOn * FIn);
        #pragma unroll
        for (int k = 0; k < 4; k++) {
            int q  = lt + k * 128;
            int fi = q >> 3;
            int c4 = (q & 7) * 4;
            cp16(xob + (fi * 32 + (c4 ^ (8 * (fi & 3)))) * 4,
                 xg + (size_t)fi * HWn + c4);
        }
        #pragma unroll
        for (int k = 0; k < 8; k++) {
            int q  = lt + k * 128;
            int fo = q >> 4;
            int c4 = (q & 15) * 4;
            cp16(wob + (fo * 64 + (c4 ^ (4 * (fo & 7)))) * 4,
                 wg + fo * FIn + c4);
        }
        asm volatile("cp.async.commit_group;" ::: "memory");
    };

    // ---------------- GEMM: 4 iterations, group = 2*it + half ----------------
    issue_half(half);

    const uint32_t bw0 = sbase + (uint32_t)(wo + (fob +      nt * 8 + r8) * 64) * 4;
    const uint32_t bw1 = sbase + (uint32_t)(wo + (fob + 16 + nt * 8 + r8) * 64) * 4;
    const int sxa = 8 * tid4;
    const int pA  = (pxb + gid) ^ sxa;
    const int pB  = (pxb + gid + 8) ^ sxa;

    for (int it = 0; it < 4; it++) {
        const int g = 2 * it + half;

        asm volatile("cp.async.wait_group 0;" ::: "memory");
        barx();

        float acc[4][4];
        #pragma unroll
        for (int n = 0; n < 4; n++)
            #pragma unroll
            for (int j = 0; j < 4; j++) acc[n][j] = 0.f;

        #pragma unroll
        for (int s = 0; s < 8; s++) {
            const int fi0 = s * 8;
            uint32_t a0 = cvt_tf32(smf[xo + (fi0 + tid4)     * 32 + pA]);
            uint32_t a1 = cvt_tf32(smf[xo + (fi0 + tid4)     * 32 + pB]);
            uint32_t a2 = cvt_tf32(smf[xo + (fi0 + 4 + tid4) * 32 + pA]);
            uint32_t a3 = cvt_tf32(smf[xo + (fi0 + 4 + tid4) * 32 + pB]);

            const uint32_t coff = 16u * (uint32_t)((2 * s + oo) ^ r8);
            uint32_t b0, b1, b2, b3, b4, b5, b6, b7;
            ldmatrix_x4(b0, b1, b2, b3, bw0 + coff);
            ldmatrix_x4(b4, b5, b6, b7, bw1 + coff);

            mma_tf32(acc[0], a0, a1, a2, a3, b0, b1);
            mma_tf32(acc[1], a0, a1, a2, a3, b2, b3);
            mma_tf32(acc[2], a0, a1, a2, a3, b4, b5);
            mma_tf32(acc[3], a0, a1, a2, a3, b6, b7);
        }

        barx();
        if (it < 3) issue_half(2 * (it + 1) + half);

        #pragma unroll
        for (int n = 0; n < 4; n++) {
            const int fo   = fob + n * 8 + 2 * tid4;
            const int row0 = g * FOn + fo;
            const int row1 = row0 + 1;
            smf[con_addr(row0, pxb + gid)]     = acc[n][0];
            smf[con_addr(row1, pxb + gid)]     = acc[n][1];
            smf[con_addr(row0, pxb + gid + 8)] = acc[n][2];
            smf[con_addr(row1, pxb + gid + 8)] = acc[n][3];
        }
    }

    __syncthreads();    // con complete, both halves

    // ---------------- routing: direct fused v-formulation --------------------
    // 8 threads per px (foc = fo-chunk of 8). Two sweeps over con:
    //   sweep1: S_fo = sum_g con;  beta_g = 0.5 * sum_fo con_g * S_fo
    //   sweep2: v_fo = sum_g alpha_g*con;  beta_g += sum_fo con_g * v_fo
    {
        const int px  = t >> 3;             // 0..31
        const int foc = t & 7;              // 8-fo chunk

        float beta[Gn];
        #pragma unroll
        for (int g = 0; g < Gn; g++) beta[g] = 0.f;

        #pragma unroll
        for (int i = 0; i < 8; i++) {
            const int fo = foc * 8 + ((i + foc) & 7);   // stagger: conflict-free
            float cg[Gn];
            #pragma unroll
            for (int g = 0; g < Gn; g++)
                cg[g] = smf[con_addr(g * FOn + fo, px)];
            float S = ((cg[0] + cg[1]) + (cg[2] + cg[3])) +
                      ((cg[4] + cg[5]) + (cg[6] + cg[7]));
            #pragma unroll
            for (int g = 0; g < Gn; g++) beta[g] += cg[g] * S;
        }
        #pragma unroll
        for (int g = 0; g < Gn; g++) {
            beta[g] += __shfl_xor_sync(0xFFFFFFFFu, beta[g], 1);
            beta[g] += __shfl_xor_sync(0xFFFFFFFFu, beta[g], 2);
            beta[g] += __shfl_xor_sync(0xFFFFFFFFu, beta[g], 4);
            beta[g] *= 0.5f;
        }

        float alpha[Gn];
        #pragma unroll
        for (int g = 0; g < Gn; g++) alpha[g] = sigmoidf_(beta[g]);

        float d[Gn];
        #pragma unroll
        for (int g = 0; g < Gn; g++) d[g] = 0.f;

        #pragma unroll
        for (int i = 0; i < 8; i++) {
            const int fo = foc * 8 + ((i + foc) & 7);
            float cg[Gn];
            #pragma unroll
            for (int g = 0; g < Gn; g++)
                cg[g] = smf[con_addr(g * FOn + fo, px)];
            float v = 0.f;
            #pragma unroll
            for (int g = 0; g < Gn; g++) v += alpha[g] * cg[g];
            #pragma unroll
            for (int g = 0; g < Gn; g++) d[g] += cg[g] * v;
        }
        #pragma unroll
        for (int g = 0; g < Gn; g++) {
            d[g] += __shfl_xor_sync(0xFFFFFFFFu, d[g], 1);
            d[g] += __shfl_xor_sync(0xFFFFFFFFu, d[g], 2);
            d[g] += __shfl_xor_sync(0xFFFFFFFFu, d[g], 4);
        }

        if (foc == 0) {
            #pragma unroll
            for (int g = 0; g < Gn; g++)
                smf[ALo + g * PXT + px] = sigmoidf_(beta[g] + d[g]);
        }
    }
    __syncthreads();

    // ---------------- final pass: f32x2 over px-pairs -------------------------
    {
        const int pp = t & 15;              // px-pair: px = 2pp, 2pp+1
        const int fq = t >> 4;              // fo quad: fo = fq*4 + i

        uint64_t al2[Gn];
        #pragma unroll
        for (int g = 0; g < Gn; g++)
            al2[g] = *reinterpret_cast<const uint64_t*>(
                &smf[ALo + g * PXT + 2 * pp]);

        float* ob = out + (size_t)bi * FOn * HWn + p0 + 2 * pp;
        #pragma unroll
        for (int i = 0; i < 4; i++) {
            const int fo = fq * 4 + i;
            uint64_t s2 = 0ull;
            #pragma unroll
            for (int g = 0; g < Gn; g++) {
                const int row = g * FOn + fo;
                const uint64_t c2 = *reinterpret_cast<const uint64_t*>(
                    &smf[CONo + row * 32 + ((2 * pp) ^ (4 * (row & 7)))]);
                s2 = f2_fma(al2[g], c2, s2);
            }
            float slo, shi;
            asm("mov.b64 {%0, %1}, %2;" : "=f"(slo), "=f"(shi) : "l"(s2));
            const float bv = __ldg(&bias[fo]);
            *reinterpret_cast<float2*>(ob + (size_t)fo * HWn) =
                make_float2(slo + bv, shi + bv);
        }
    }
}

extern "C" void kernel_launch(void* const* d_in, const int* in_sizes, int n_in,
                              void* d_out, int out_size)
{
    const float* x = nullptr;
    const float* w = nullptr;
    const float* b = nullptr;
    for (int i = 0; i < n_in; i++) {
        if (in_sizes[i] == Bn * Gn * FIn * HWn)      x = (const float*)d_in[i];
        else if (in_sizes[i] == Gn * FOn * FIn)      w = (const float*)d_in[i];
        else if (in_sizes[i] == FOn)                 b = (const float*)d_in[i];
    }
    float* out = (float*)d_out;

    static bool attr_set = false;
    if (!attr_set) {
        cudaFuncSetAttribute(dynrout_mma_kernel,
                             cudaFuncAttributeMaxDynamicSharedMemorySize, SMEM_BYTES);
        attr_set = true;
    }

    wconv_kernel<<<(Gn * FOn * FIn) / 256, 256>>>(w);

    const int n_ctas = (Bn * HWn) / PXT;   // 2048
    dynrout_mma_kernel<<<n_ctas, THREADS, SMEM_BYTES>>>(x, b, out);
}